// round 2
// baseline (speedup 1.0000x reference)
#include <cuda_runtime.h>
#include <math.h>

#define DIM   2048
#define INTER 1408
#define NE    15
#define TMAX  4096

// ---------------- device scratch (no allocations allowed) ----------------
__device__ int   g_count[NE];
__device__ int   g_offset[NE + 1];
__device__ int   g_tok[NE * TMAX];
__device__ float g_wt[NE * TMAX];
// h rows: [0, 2T) routed (compacted by expert via g_offset), [2T, 3T) shared
__device__ float g_h[(size_t)3 * TMAX * INTER];

// ---------------- reset (graph replays re-run everything) ----------------
__global__ void reset_kernel() {
    if (threadIdx.x < NE) g_count[threadIdx.x] = 0;
}

// ---------------- gating: logits -> softmax -> top2 -> expert lists ------
__global__ void gate_kernel(const float* __restrict__ x,
                            const float* __restrict__ gw, int T) {
    int t = blockIdx.x;
    const float* xt = x + (size_t)t * DIM;
    float acc[NE];
#pragma unroll
    for (int e = 0; e < NE; e++) acc[e] = 0.f;
    for (int d = threadIdx.x; d < DIM; d += 128) {
        float xv = xt[d];
#pragma unroll
        for (int e = 0; e < NE; e++) acc[e] += xv * gw[e * DIM + d];
    }
#pragma unroll
    for (int e = 0; e < NE; e++)
        for (int o = 16; o > 0; o >>= 1)
            acc[e] += __shfl_down_sync(0xffffffffu, acc[e], o);

    __shared__ float s[NE][4];
    int lane = threadIdx.x & 31, w = threadIdx.x >> 5;
    if (lane == 0) {
#pragma unroll
        for (int e = 0; e < NE; e++) s[e][w] = acc[e];
    }
    __syncthreads();
    if (threadIdx.x == 0) {
        float v[NE], p[NE];
        float mx = -1e30f;
#pragma unroll
        for (int e = 0; e < NE; e++) {
            v[e] = s[e][0] + s[e][1] + s[e][2] + s[e][3];
            mx = fmaxf(mx, v[e]);
        }
        float sum = 0.f;
#pragma unroll
        for (int e = 0; e < NE; e++) { p[e] = expf(v[e] - mx); sum += p[e]; }
        // top-2 (strict >, lowest index wins ties, matching jax top_k)
        int i1 = 0;
        for (int e = 1; e < NE; e++) if (v[e] > v[i1]) i1 = e;
        int i2 = (i1 == 0) ? 1 : 0;
        for (int e = 0; e < NE; e++) if (e != i1 && v[e] > v[i2]) i2 = e;
        float inv = 1.f / sum;
        int idx[2] = {i1, i2};
#pragma unroll
        for (int ssel = 0; ssel < 2; ssel++) {
            int e = idx[ssel];
            int pos = atomicAdd(&g_count[e], 1);
            g_tok[e * TMAX + pos] = t;
            g_wt[e * TMAX + pos]  = p[e] * inv;
        }
    }
}

__global__ void offset_kernel() {
    int s = 0;
    for (int e = 0; e < NE; e++) { g_offset[e] = s; s += g_count[e]; }
    g_offset[NE] = s;
}

// ---------------- up projection: h = silu(x@W1^T) * (x@W3^T) -------------
// grid: (INTER/64, ceil(T/64), 16). z==15 => shared expert over all tokens.
__global__ __launch_bounds__(256) void up_kernel(
    const float* __restrict__ x,
    const float* __restrict__ w1, const float* __restrict__ w3,
    const float* __restrict__ sw1, const float* __restrict__ sw3, int T) {
    int z = blockIdx.z;
    bool is_shared = (z == NE);
    int count, hbase;
    const float *W1, *W3;
    if (is_shared) {
        count = T; hbase = 2 * T; W1 = sw1; W3 = sw3;
    } else {
        count = g_count[z]; hbase = g_offset[z];
        W1 = w1 + (size_t)z * INTER * DIM;
        W3 = w3 + (size_t)z * INTER * DIM;
    }
    int row0 = blockIdx.y * 64;
    if (row0 >= count) return;
    int n0 = blockIdx.x * 64;

    __shared__ float As[64][17], B1s[64][17], B3s[64][17];
    __shared__ int stok[64];
    int tid = threadIdx.x;
    if (tid < 64) {
        int r = row0 + tid;
        stok[tid] = (r < count) ? (is_shared ? r : g_tok[z * TMAX + r]) : 0;
    }
    __syncthreads();

    float a1[4][4] = {}, a3[4][4] = {};
    int tx = tid & 15, ty = tid >> 4;

    for (int kk = 0; kk < DIM; kk += 16) {
#pragma unroll
        for (int i = 0; i < 4; i++) {
            int lin = tid + i * 256;
            int m = lin >> 4, k = lin & 15;
            As[m][k]  = x[(size_t)stok[m] * DIM + kk + k];
            B1s[m][k] = W1[(size_t)(n0 + m) * DIM + kk + k];
            B3s[m][k] = W3[(size_t)(n0 + m) * DIM + kk + k];
        }
        __syncthreads();
#pragma unroll
        for (int k = 0; k < 16; k++) {
            float av[4], b1v[4], b3v[4];
#pragma unroll
            for (int i = 0; i < 4; i++) av[i] = As[ty * 4 + i][k];
#pragma unroll
            for (int j = 0; j < 4; j++) {
                b1v[j] = B1s[tx * 4 + j][k];
                b3v[j] = B3s[tx * 4 + j][k];
            }
#pragma unroll
            for (int i = 0; i < 4; i++)
#pragma unroll
                for (int j = 0; j < 4; j++) {
                    a1[i][j] += av[i] * b1v[j];
                    a3[i][j] += av[i] * b3v[j];
                }
        }
        __syncthreads();
    }

#pragma unroll
    for (int i = 0; i < 4; i++) {
        int r = row0 + ty * 4 + i;
        if (r < count) {
            size_t base = (size_t)(hbase + r) * INTER + n0 + tx * 4;
#pragma unroll
            for (int j = 0; j < 4; j++) {
                float u = a1[i][j];
                float h = (u / (1.f + expf(-u))) * a3[i][j];
                g_h[base + j] = h;
            }
        }
    }
}

// ---------------- down projection, shared expert (initializes out) -------
__global__ __launch_bounds__(256) void down_shared_kernel(
    float* __restrict__ out, const float* __restrict__ sw2, int T) {
    int row0 = blockIdx.y * 64;
    int n0 = blockIdx.x * 64;
    int hbase = 2 * T;

    __shared__ float As[64][17], Bs[64][17];
    float acc[4][4] = {};
    int tid = threadIdx.x, tx = tid & 15, ty = tid >> 4;

    for (int kk = 0; kk < INTER; kk += 16) {
#pragma unroll
        for (int i = 0; i < 4; i++) {
            int lin = tid + i * 256;
            int m = lin >> 4, k = lin & 15;
            As[m][k] = g_h[(size_t)(hbase + row0 + m) * INTER + kk + k];
            Bs[m][k] = sw2[(size_t)(n0 + m) * INTER + kk + k];
        }
        __syncthreads();
#pragma unroll
        for (int k = 0; k < 16; k++) {
            float av[4], bv[4];
#pragma unroll
            for (int i = 0; i < 4; i++) av[i] = As[ty * 4 + i][k];
#pragma unroll
            for (int j = 0; j < 4; j++) bv[j] = Bs[tx * 4 + j][k];
#pragma unroll
            for (int i = 0; i < 4; i++)
#pragma unroll
                for (int j = 0; j < 4; j++) acc[i][j] += av[i] * bv[j];
        }
        __syncthreads();
    }
#pragma unroll
    for (int i = 0; i < 4; i++) {
        size_t base = (size_t)(row0 + ty * 4 + i) * DIM + n0 + tx * 4;
#pragma unroll
        for (int j = 0; j < 4; j++) out[base + j] = acc[i][j];
    }
}

// ---------------- down projection, routed experts (atomic accumulate) ----
__global__ __launch_bounds__(256) void down_routed_kernel(
    float* __restrict__ out, const float* __restrict__ w2, int T) {
    int z = blockIdx.z;
    int count = g_count[z];
    int row0 = blockIdx.y * 64;
    if (row0 >= count) return;
    int hbase = g_offset[z];
    int n0 = blockIdx.x * 64;
    const float* W2 = w2 + (size_t)z * DIM * INTER;

    __shared__ float As[64][17], Bs[64][17];
    __shared__ int stok[64];
    __shared__ float swt[64];
    int tid = threadIdx.x, tx = tid & 15, ty = tid >> 4;
    if (tid < 64) {
        int r = row0 + tid;
        if (r < count) { stok[tid] = g_tok[z * TMAX + r]; swt[tid] = g_wt[z * TMAX + r]; }
        else           { stok[tid] = 0;                   swt[tid] = 0.f; }
    }
    __syncthreads();

    float acc[4][4] = {};
    for (int kk = 0; kk < INTER; kk += 16) {
#pragma unroll
        for (int i = 0; i < 4; i++) {
            int lin = tid + i * 256;
            int m = lin >> 4, k = lin & 15;
            int r = row0 + m;
            int hr = hbase + ((r < count) ? r : (count - 1));  // clamp: safe read
            As[m][k] = g_h[(size_t)hr * INTER + kk + k];
            Bs[m][k] = W2[(size_t)(n0 + m) * INTER + kk + k];
        }
        __syncthreads();
#pragma unroll
        for (int k = 0; k < 16; k++) {
            float av[4], bv[4];
#pragma unroll
            for (int i = 0; i < 4; i++) av[i] = As[ty * 4 + i][k];
#pragma unroll
            for (int j = 0; j < 4; j++) bv[j] = Bs[tx * 4 + j][k];
#pragma unroll
            for (int i = 0; i < 4; i++)
#pragma unroll
                for (int j = 0; j < 4; j++) acc[i][j] += av[i] * bv[j];
        }
        __syncthreads();
    }
#pragma unroll
    for (int i = 0; i < 4; i++) {
        int m = ty * 4 + i;
        int r = row0 + m;
        if (r < count) {
            float wgt = swt[m];
            size_t base = (size_t)stok[m] * DIM + n0 + tx * 4;
#pragma unroll
            for (int j = 0; j < 4; j++)
                atomicAdd(&out[base + j], acc[i][j] * wgt);
        }
    }
}

// ---------------- entry point --------------------------------------------
extern "C" void kernel_launch(void* const* d_in, const int* in_sizes, int n_in,
                              void* d_out, int out_size) {
    const float* x   = (const float*)d_in[0];
    const float* gw  = (const float*)d_in[1];
    const float* w1  = (const float*)d_in[2];
    const float* w3  = (const float*)d_in[3];
    const float* w2  = (const float*)d_in[4];
    const float* sw1 = (const float*)d_in[5];
    const float* sw3 = (const float*)d_in[6];
    const float* sw2 = (const float*)d_in[7];
    float* out = (float*)d_out;

    int T = in_sizes[0] / DIM;  // 4096

    reset_kernel<<<1, 32>>>();
    gate_kernel<<<T, 128>>>(x, gw, T);
    offset_kernel<<<1, 1>>>();

    dim3 gup(INTER / 64, (T + 63) / 64, NE + 1);
    up_kernel<<<gup, 256>>>(x, w1, w3, sw1, sw3, T);

    dim3 gds(DIM / 64, (T + 63) / 64);
    down_shared_kernel<<<gds, 256>>>(out, sw2, T);

    dim3 gdr(DIM / 64, (T + 63) / 64, NE);
    down_routed_kernel<<<gdr, 256>>>(out, w2, T);
}

// round 4
// speedup vs baseline: 4.4167x; 4.4167x over previous
#include <cuda_runtime.h>
#include <cuda_fp16.h>
#include <math.h>
#include <stdint.h>

#define DIM   2048
#define INTER 1408
#define NE    15
#define TMAX  4096
#define KC    32
// smem tile offsets (bytes): each tile 128 rows x 32 fp16 = 8KB
#define AH 0
#define AL 8192
#define BH 16384
#define BL 24576
#define BUFSZ 32768

// ---------------- device scratch ----------------
__device__ int   g_count[NE];
__device__ int   g_offset[NE + 1];
__device__ int   g_tok[NE * TMAX];
__device__ float g_wt[NE * TMAX];
__device__ float g_roww[3 * TMAX];
__device__ float g_u[(size_t)2 * 3 * TMAX * INTER];   // u1, u3
__device__ __half g_hh[(size_t)3 * TMAX * INTER];     // h hi
__device__ __half g_hl[(size_t)3 * TMAX * INTER];     // h lo

// ---------------- helpers ----------------
__device__ __forceinline__ uint32_t smem_u32(const void* p) {
    uint32_t a;
    asm("{ .reg .u64 t; cvta.to.shared.u64 t, %1; cvt.u32.u64 %0, t; }" : "=r"(a) : "l"(p));
    return a;
}
// swizzled byte offset inside a 128x32 fp16 tile (64B rows, 4 chunks of 16B)
__device__ __forceinline__ uint32_t toff(uint32_t r, uint32_t c) {
    return r * 64u + ((c ^ ((r >> 1) & 3u)) << 4);
}
__device__ __forceinline__ void ldsm4(uint32_t r[4], uint32_t a) {
    asm volatile("ldmatrix.sync.aligned.m8n8.x4.shared.b16 {%0,%1,%2,%3},[%4];"
                 : "=r"(r[0]), "=r"(r[1]), "=r"(r[2]), "=r"(r[3]) : "r"(a));
}
__device__ __forceinline__ void mma_f16(float c[4], const uint32_t a[4], const uint32_t b[2]) {
    asm volatile("mma.sync.aligned.m16n8k16.row.col.f32.f16.f16.f32 "
                 "{%0,%1,%2,%3},{%4,%5,%6,%7},{%8,%9},{%0,%1,%2,%3};"
                 : "+f"(c[0]), "+f"(c[1]), "+f"(c[2]), "+f"(c[3])
                 : "r"(a[0]), "r"(a[1]), "r"(a[2]), "r"(a[3]), "r"(b[0]), "r"(b[1]));
}
__device__ __forceinline__ void cvt_split(float4 v, uint2& H, uint2& L) {
    __half2 h01 = __floats2half2_rn(v.x, v.y);
    __half2 h23 = __floats2half2_rn(v.z, v.w);
    float2 f01 = __half22float2(h01), f23 = __half22float2(h23);
    __half2 l01 = __floats2half2_rn(v.x - f01.x, v.y - f01.y);
    __half2 l23 = __floats2half2_rn(v.z - f23.x, v.w - f23.y);
    H.x = *(uint32_t*)&h01; H.y = *(uint32_t*)&h23;
    L.x = *(uint32_t*)&l01; L.y = *(uint32_t*)&l23;
}

// one k-chunk of MMA work on buffer at smem byte base `base` (3-term split)
__device__ __forceinline__ void compute_iter(float acc[2][8][4], uint32_t base,
                                             int wm, int wn, int arow, int asel,
                                             int brow, int bsel) {
#pragma unroll
    for (int ks = 0; ks < 2; ks++) {
        uint32_t ah[2][4], al[2][4];
#pragma unroll
        for (int mt = 0; mt < 2; mt++) {
            uint32_t ao = toff((uint32_t)(wm + mt * 16 + arow), (uint32_t)(ks * 2 + asel));
            ldsm4(ah[mt], base + AH + ao);
            ldsm4(al[mt], base + AL + ao);
        }
#pragma unroll
        for (int np = 0; np < 4; np++) {
            uint32_t bo = toff((uint32_t)(wn + np * 16 + brow), (uint32_t)(ks * 2 + bsel));
            uint32_t bh[4], bl[4];
            ldsm4(bh, base + BH + bo);
            ldsm4(bl, base + BL + bo);
#pragma unroll
            for (int mt = 0; mt < 2; mt++)
#pragma unroll
                for (int ns = 0; ns < 2; ns++) {
                    float* c = acc[mt][np * 2 + ns];
                    mma_f16(c, ah[mt], bh + ns * 2);
                    mma_f16(c, ah[mt], bl + ns * 2);
                    mma_f16(c, al[mt], bh + ns * 2);
                }
        }
    }
}

// ---------------- gating ----------------
__global__ void reset_kernel() { if (threadIdx.x < NE) g_count[threadIdx.x] = 0; }

__global__ void gate_kernel(const float* __restrict__ x,
                            const float* __restrict__ gw, int T) {
    int t = blockIdx.x;
    const float* xt = x + (size_t)t * DIM;
    float acc[NE];
#pragma unroll
    for (int e = 0; e < NE; e++) acc[e] = 0.f;
    for (int d = threadIdx.x; d < DIM; d += 128) {
        float xv = xt[d];
#pragma unroll
        for (int e = 0; e < NE; e++) acc[e] += xv * gw[e * DIM + d];
    }
#pragma unroll
    for (int e = 0; e < NE; e++)
        for (int o = 16; o > 0; o >>= 1)
            acc[e] += __shfl_down_sync(0xffffffffu, acc[e], o);
    __shared__ float s[NE][4];
    int lane = threadIdx.x & 31, w = threadIdx.x >> 5;
    if (lane == 0) {
#pragma unroll
        for (int e = 0; e < NE; e++) s[e][w] = acc[e];
    }
    __syncthreads();
    if (threadIdx.x == 0) {
        float v[NE], p[NE];
        float mx = -1e30f;
#pragma unroll
        for (int e = 0; e < NE; e++) {
            v[e] = s[e][0] + s[e][1] + s[e][2] + s[e][3];
            mx = fmaxf(mx, v[e]);
        }
        float sum = 0.f;
#pragma unroll
        for (int e = 0; e < NE; e++) { p[e] = expf(v[e] - mx); sum += p[e]; }
        int i1 = 0;
        for (int e = 1; e < NE; e++) if (v[e] > v[i1]) i1 = e;
        int i2 = (i1 == 0) ? 1 : 0;
        for (int e = 0; e < NE; e++) if (e != i1 && v[e] > v[i2]) i2 = e;
        float inv = 1.f / sum;
        int idx[2] = {i1, i2};
#pragma unroll
        for (int ssel = 0; ssel < 2; ssel++) {
            int e = idx[ssel];
            int pos = atomicAdd(&g_count[e], 1);
            g_tok[e * TMAX + pos] = t;
            g_wt[e * TMAX + pos]  = p[e] * inv;
        }
    }
}

__global__ void offset_kernel() {
    int s = 0;
    for (int e = 0; e < NE; e++) { g_offset[e] = s; s += g_count[e]; }
    g_offset[NE] = s;
}

// row -> routing weight (compacted h-row space); shared rows -> 1.0
__global__ void roww_kernel(int T) {
    int r = blockIdx.x * 256 + threadIdx.x;
    if (r >= 3 * T) return;
    if (r >= 2 * T) { g_roww[r] = 1.f; return; }
    int e = 0;
    for (int i = 1; i < NE; i++) if (r >= g_offset[i]) e = i;
    g_roww[r] = g_wt[e * TMAX + (r - g_offset[e])];
}

// ---------------- up GEMM: U[which] = X_gathered @ W^T ----------------
// grid (INTER/128=11, 32, 32); z: expert = z>>1 (15 == shared), which = z&1
__global__ __launch_bounds__(256, 1) void gemm_up(
    const float* __restrict__ x,
    const float* __restrict__ w1, const float* __restrict__ w3,
    const float* __restrict__ sw1, const float* __restrict__ sw3, int T) {
    int z = blockIdx.z;
    int e = z >> 1, which = z & 1;
    bool se = (e == NE);
    int count = se ? T : g_count[e];
    int row0 = blockIdx.y * 128;
    if (row0 >= count) return;
    int hbase = se ? 2 * T : g_offset[e];
    const float* W = which ? (se ? sw3 : w3 + (size_t)e * INTER * DIM)
                           : (se ? sw1 : w1 + (size_t)e * INTER * DIM);
    float* U = g_u + (size_t)which * 3 * TMAX * INTER;
    int n0 = blockIdx.x * 128;

    extern __shared__ __align__(128) char smem[];
    __shared__ int stok[128];
    int tid = threadIdx.x, wid = tid >> 5, lane = tid & 31;
    if (tid < 128) {
        int r = row0 + tid;
        int rc = (r < count) ? r : count - 1;
        stok[tid] = se ? rc : g_tok[e * TMAX + rc];
    }
    __syncthreads();

    const float *aptr[4], *bptr[4];
    uint32_t soff[4];
#pragma unroll
    for (int i = 0; i < 4; i++) {
        int idx = tid + i * 256;
        int r = idx >> 3, c4 = idx & 7;
        aptr[i] = x + (size_t)stok[r] * DIM + (c4 << 2);
        bptr[i] = W + (size_t)(n0 + r) * DIM + (c4 << 2);
        soff[i] = toff((uint32_t)r, (uint32_t)(c4 >> 1)) + (uint32_t)(c4 & 1) * 8;
    }

    float4 ra[4], rb[4];
#pragma unroll
    for (int i = 0; i < 4; i++) { ra[i] = *(const float4*)aptr[i]; rb[i] = *(const float4*)bptr[i]; }
#pragma unroll
    for (int i = 0; i < 4; i++) {
        uint2 H, L;
        cvt_split(ra[i], H, L);
        *(uint2*)(smem + AH + soff[i]) = H;
        *(uint2*)(smem + AL + soff[i]) = L;
        cvt_split(rb[i], H, L);
        *(uint2*)(smem + BH + soff[i]) = H;
        *(uint2*)(smem + BL + soff[i]) = L;
    }
    __syncthreads();

    uint32_t sb = smem_u32(smem);
    int arow = lane & 15, asel = lane >> 4;
    int brow = (lane & 7) + ((lane & 16) >> 1), bsel = (lane >> 3) & 1;
    int wm = (wid & 3) * 32, wn = (wid >> 2) * 64;

    float acc[2][8][4] = {};
    const int NIT = DIM / KC;  // 64
    for (int it = 0; it < NIT; it++) {
        if (it + 1 < NIT) {
            int kk = (it + 1) * KC;
#pragma unroll
            for (int i = 0; i < 4; i++) {
                ra[i] = *(const float4*)(aptr[i] + kk);
                rb[i] = *(const float4*)(bptr[i] + kk);
            }
        }
        compute_iter(acc, sb + (uint32_t)(it & 1) * BUFSZ, wm, wn, arow, asel, brow, bsel);
        __syncthreads();
        if (it + 1 < NIT) {
            char* d = smem + ((it + 1) & 1) * BUFSZ;
#pragma unroll
            for (int i = 0; i < 4; i++) {
                uint2 H, L;
                cvt_split(ra[i], H, L);
                *(uint2*)(d + AH + soff[i]) = H;
                *(uint2*)(d + AL + soff[i]) = L;
                cvt_split(rb[i], H, L);
                *(uint2*)(d + BH + soff[i]) = H;
                *(uint2*)(d + BL + soff[i]) = L;
            }
            __syncthreads();
        }
    }

#pragma unroll
    for (int mt = 0; mt < 2; mt++)
#pragma unroll
        for (int j = 0; j < 8; j++)
#pragma unroll
            for (int h = 0; h < 2; h++) {
                int lr = wm + mt * 16 + (lane >> 2) + h * 8;
                if (row0 + lr < count) {
                    int col = n0 + wn + j * 8 + (lane & 3) * 2;
                    float2 v = make_float2(acc[mt][j][h * 2], acc[mt][j][h * 2 + 1]);
                    *(float2*)(U + (size_t)(hbase + row0 + lr) * INTER + col) = v;
                }
            }
}

// ---------------- combine: h = silu(u1)*u3*wt, split to fp16 hi/lo --------
__global__ void combine_kernel(int T) {
    size_t i = ((size_t)blockIdx.x * 256 + threadIdx.x) * 4;
    size_t total = (size_t)3 * T * INTER;
    if (i >= total) return;
    int row = (int)(i / INTER);
    float wt = g_roww[row];
    float4 u1 = *(const float4*)(g_u + i);
    float4 u3 = *(const float4*)(g_u + (size_t)3 * TMAX * INTER + i);
    float4 h;
    h.x = (u1.x / (1.f + expf(-u1.x))) * u3.x * wt;
    h.y = (u1.y / (1.f + expf(-u1.y))) * u3.y * wt;
    h.z = (u1.z / (1.f + expf(-u1.z))) * u3.z * wt;
    h.w = (u1.w / (1.f + expf(-u1.w))) * u3.w * wt;
    uint2 H, L;
    cvt_split(h, H, L);
    *(uint2*)(g_hh + i) = H;
    *(uint2*)(g_hl + i) = L;
}

// ---------------- down GEMM: out (+)= H @ W2^T ----------------------------
__global__ __launch_bounds__(256, 1) void gemm_down(
    const float* __restrict__ w2, float* __restrict__ out, int T, int routed) {
    int z = blockIdx.z;
    int count, hbase;
    const float* B;
    if (routed) {
        count = g_count[z]; hbase = g_offset[z];
        B = w2 + (size_t)z * DIM * INTER;
    } else {
        count = T; hbase = 2 * T; B = w2;
    }
    int row0 = blockIdx.y * 128;
    if (row0 >= count) return;
    int n0 = blockIdx.x * 128;

    extern __shared__ __align__(128) char smem[];
    __shared__ int stok[128];
    int tid = threadIdx.x, wid = tid >> 5, lane = tid & 31;
    if (tid < 128) {
        int r = row0 + tid;
        int rc = (r < count) ? r : count - 1;
        stok[tid] = routed ? g_tok[z * TMAX + rc] : rc;
    }
    __syncthreads();

    const __half *ahp[2], *alp[2];
    uint32_t soffA[2];
#pragma unroll
    for (int i = 0; i < 2; i++) {
        int idx = tid + i * 256;
        int r = idx >> 2, chunk = idx & 3;
        int rr = row0 + r;
        int hr = hbase + ((rr < count) ? rr : count - 1);
        ahp[i] = g_hh + (size_t)hr * INTER + chunk * 8;
        alp[i] = g_hl + (size_t)hr * INTER + chunk * 8;
        soffA[i] = toff((uint32_t)r, (uint32_t)chunk);
    }
    const float* bptr[4];
    uint32_t soffB[4];
#pragma unroll
    for (int i = 0; i < 4; i++) {
        int idx = tid + i * 256;
        int r = idx >> 3, c4 = idx & 7;
        bptr[i] = B + (size_t)(n0 + r) * INTER + (c4 << 2);
        soffB[i] = toff((uint32_t)r, (uint32_t)(c4 >> 1)) + (uint32_t)(c4 & 1) * 8;
    }

    uint4 rah[2], ral[2];
    float4 rb[4];
#pragma unroll
    for (int i = 0; i < 2; i++) { rah[i] = *(const uint4*)ahp[i]; ral[i] = *(const uint4*)alp[i]; }
#pragma unroll
    for (int i = 0; i < 4; i++) rb[i] = *(const float4*)bptr[i];
#pragma unroll
    for (int i = 0; i < 2; i++) {
        *(uint4*)(smem + AH + soffA[i]) = rah[i];
        *(uint4*)(smem + AL + soffA[i]) = ral[i];
    }
#pragma unroll
    for (int i = 0; i < 4; i++) {
        uint2 H, L;
        cvt_split(rb[i], H, L);
        *(uint2*)(smem + BH + soffB[i]) = H;
        *(uint2*)(smem + BL + soffB[i]) = L;
    }
    __syncthreads();

    uint32_t sb = smem_u32(smem);
    int arow = lane & 15, asel = lane >> 4;
    int brow = (lane & 7) + ((lane & 16) >> 1), bsel = (lane >> 3) & 1;
    int wm = (wid & 3) * 32, wn = (wid >> 2) * 64;

    float acc[2][8][4] = {};
    const int NIT = INTER / KC;  // 44
    for (int it = 0; it < NIT; it++) {
        if (it + 1 < NIT) {
            int kk = (it + 1) * KC;
#pragma unroll
            for (int i = 0; i < 2; i++) {
                rah[i] = *(const uint4*)(ahp[i] + kk);
                ral[i] = *(const uint4*)(alp[i] + kk);
            }
#pragma unroll
            for (int i = 0; i < 4; i++) rb[i] = *(const float4*)(bptr[i] + kk);
        }
        compute_iter(acc, sb + (uint32_t)(it & 1) * BUFSZ, wm, wn, arow, asel, brow, bsel);
        __syncthreads();
        if (it + 1 < NIT) {
            char* d = smem + ((it + 1) & 1) * BUFSZ;
#pragma unroll
            for (int i = 0; i < 2; i++) {
                *(uint4*)(d + AH + soffA[i]) = rah[i];
                *(uint4*)(d + AL + soffA[i]) = ral[i];
            }
#pragma unroll
            for (int i = 0; i < 4; i++) {
                uint2 H, L;
                cvt_split(rb[i], H, L);
                *(uint2*)(d + BH + soffB[i]) = H;
                *(uint2*)(d + BL + soffB[i]) = L;
            }
            __syncthreads();
        }
    }

#pragma unroll
    for (int mt = 0; mt < 2; mt++)
#pragma unroll
        for (int j = 0; j < 8; j++)
#pragma unroll
            for (int h = 0; h < 2; h++) {
                int lr = wm + mt * 16 + (lane >> 2) + h * 8;
                if (row0 + lr < count) {
                    int col = n0 + wn + j * 8 + (lane & 3) * 2;
                    size_t ob = (size_t)stok[lr] * DIM + col;
                    if (routed) {
                        atomicAdd(&out[ob],     acc[mt][j][h * 2]);
                        atomicAdd(&out[ob + 1], acc[mt][j][h * 2 + 1]);
                    } else {
                        *(float2*)(out + ob) =
                            make_float2(acc[mt][j][h * 2], acc[mt][j][h * 2 + 1]);
                    }
                }
            }
}

// ---------------- entry point ----------------------------------------------
extern "C" void kernel_launch(void* const* d_in, const int* in_sizes, int n_in,
                              void* d_out, int out_size) {
    const float* x   = (const float*)d_in[0];
    const float* gw  = (const float*)d_in[1];
    const float* w1  = (const float*)d_in[2];
    const float* w3  = (const float*)d_in[3];
    const float* w2  = (const float*)d_in[4];
    const float* sw1 = (const float*)d_in[5];
    const float* sw3 = (const float*)d_in[6];
    const float* sw2 = (const float*)d_in[7];
    float* out = (float*)d_out;

    int T = in_sizes[0] / DIM;  // 4096

    cudaFuncSetAttribute(gemm_up,   cudaFuncAttributeMaxDynamicSharedMemorySize, 2 * BUFSZ);
    cudaFuncSetAttribute(gemm_down, cudaFuncAttributeMaxDynamicSharedMemorySize, 2 * BUFSZ);

    reset_kernel<<<1, 32>>>();
    gate_kernel<<<T, 128>>>(x, gw, T);
    offset_kernel<<<1, 1>>>();
    roww_kernel<<<(3 * T + 255) / 256, 256>>>(T);

    dim3 gup(INTER / 128, (T + 127) / 128, 2 * (NE + 1));
    gemm_up<<<gup, 256, 2 * BUFSZ>>>(x, w1, w3, sw1, sw3, T);

    size_t total4 = (size_t)3 * T * INTER / 4;
    combine_kernel<<<(unsigned)((total4 + 255) / 256), 256>>>(T);

    dim3 gds(DIM / 128, (T + 127) / 128, 1);
    gemm_down<<<gds, 256, 2 * BUFSZ>>>(sw2, out, T, 0);

    dim3 gdr(DIM / 128, (T + 127) / 128, NE);
    gemm_down<<<gdr, 256, 2 * BUFSZ>>>(w2, out, T, 1);
}